// round 3
// baseline (speedup 1.0000x reference)
#include <cuda_runtime.h>
#include <cuda_bf16.h>
#include <math.h>

// ---------------- problem constants ----------------
#define BATCH 16
#define NNODE 64
#define BN    1024      // BATCH*NNODE
#define TT    256
#define DD    128
#define HH    128
#define G3    384       // 3*H
#define TD    32768     // T*D

// ---------------- device scratch (NEVER referenced from host code!) ----------------
__device__ float g_gi[BN * TT * G3];        // 402 MB  gate inputs (reused both layers)
__device__ float g_hs[BN * TT * HH];        // 134 MB  layer-0 hidden sequence
__device__ float g_hmean[BN * HH];
__device__ float g_Gp[BATCH * 16 * NNODE * NNODE];
__device__ float g_sim[BATCH * NNODE * NNODE];
__device__ float g_A[BATCH * NNODE * NNODE];
__device__ float g_w[BATCH * NNODE * NNODE];
__device__ float g_h1[BN * HH];
__device__ float g_h2[BN * HH];

// ================= GEMM: g_gi[M,384] = A[M,128] @ W[384,128]^T + bias =================
// useHs=0: A = x_ext (harness ptr);  useHs=1: A = g_hs (device symbol, resolved in device code)
__global__ void __launch_bounds__(256) k_gemm384(const float* x_ext,
                                                 const float* __restrict__ W,
                                                 const float* __restrict__ bias,
                                                 int useHs)
{
    const float* A = useHs ? (const float*)g_hs : x_ext;
    __shared__ float As[16][132];
    __shared__ float Bs[16][132];
    const int bm = blockIdx.x * 128;
    const int bn = blockIdx.y * 128;
    const int tid = threadIdx.x;
    const int tr = (tid >> 4) * 8;
    const int tc = (tid & 15) * 8;
    float acc[8][8] = {};

    for (int k0 = 0; k0 < 128; k0 += 16) {
#pragma unroll
        for (int l = 0; l < 2; l++) {
            int idx = tid + l * 256;           // 0..511
            int r = idx >> 2;
            int c4 = (idx & 3) * 4;
            float4 va = *(const float4*)&A[(size_t)(bm + r) * 128 + k0 + c4];
            As[c4 + 0][r] = va.x; As[c4 + 1][r] = va.y;
            As[c4 + 2][r] = va.z; As[c4 + 3][r] = va.w;
            float4 vb = *(const float4*)&W[(size_t)(bn + r) * 128 + k0 + c4];
            Bs[c4 + 0][r] = vb.x; Bs[c4 + 1][r] = vb.y;
            Bs[c4 + 2][r] = vb.z; Bs[c4 + 3][r] = vb.w;
        }
        __syncthreads();
#pragma unroll
        for (int k = 0; k < 16; k++) {
            float a[8], b[8];
            *(float4*)&a[0] = *(const float4*)&As[k][tr];
            *(float4*)&a[4] = *(const float4*)&As[k][tr + 4];
            *(float4*)&b[0] = *(const float4*)&Bs[k][tc];
            *(float4*)&b[4] = *(const float4*)&Bs[k][tc + 4];
#pragma unroll
            for (int i = 0; i < 8; i++)
#pragma unroll
                for (int j = 0; j < 8; j++)
                    acc[i][j] = fmaf(a[i], b[j], acc[i][j]);
        }
        __syncthreads();
    }
#pragma unroll
    for (int i = 0; i < 8; i++) {
#pragma unroll
        for (int j = 0; j < 8; j++) acc[i][j] += bias[bn + tc + j];
        float* cp = &g_gi[(size_t)(bm + tr + i) * G3 + bn + tc];
        *(float4*)&cp[0] = *(float4*)&acc[i][0];
        *(float4*)&cp[4] = *(float4*)&acc[i][4];
    }
}

// ================= GRU scan: persistent over T, 8 rows / CTA =================
// dynamic smem: whh_s[128][384] (k-major) + h_s[8][128]  -> 200704 B (opt-in)
__global__ void __launch_bounds__(256, 1) k_gru_scan(const float* __restrict__ Whh,
                                                     const float* __restrict__ bhh,
                                                     int writeHs)
{
    extern __shared__ float sm[];
    float* whh_s = sm;                 // 49152 floats, layout [k][g]
    float* h_s = sm + 49152;           // 8*128

    const int tid = threadIdx.x;
    const int gpart = tid & 127;
    const int half = tid >> 7;         // 0: rows 0-3 (warps 0-3), 1: rows 4-7
    const int r0 = blockIdx.x * 8;

    for (int i = tid; i < 49152; i += 256) {
        int g = i >> 7, k = i & 127;
        whh_s[k * G3 + g] = Whh[i];
    }
#pragma unroll
    for (int mm = 0; mm < 4; mm++) h_s[(half * 4 + mm) * 128 + gpart] = 0.f;
    __syncthreads();

    const float b0 = bhh[gpart];
    const float b1 = bhh[gpart + 128];
    const float b2 = bhh[gpart + 256];
    float msum[4] = {0.f, 0.f, 0.f, 0.f};

    const float* gi_base = g_gi + (size_t)(r0 + half * 4) * (TT * G3);

    for (int t = 0; t < TT; t++) {
        float ir[4], iz[4], inp[4];
#pragma unroll
        for (int mm = 0; mm < 4; mm++) {
            const float* gp = gi_base + (size_t)mm * (TT * G3) + (size_t)t * G3;
            ir[mm]  = gp[gpart];
            iz[mm]  = gp[gpart + 128];
            inp[mm] = gp[gpart + 256];
        }
        float a0[4] = {}, a1[4] = {}, a2[4] = {};
#pragma unroll 4
        for (int k = 0; k < 128; k += 4) {
            float4 hv[4];
#pragma unroll
            for (int mm = 0; mm < 4; mm++)
                hv[mm] = *(const float4*)&h_s[(half * 4 + mm) * 128 + k];
#pragma unroll
            for (int kk = 0; kk < 4; kk++) {
                const float* wrow = &whh_s[(k + kk) * G3 + gpart];
                float w0 = wrow[0], w1 = wrow[128], w2 = wrow[256];
#pragma unroll
                for (int mm = 0; mm < 4; mm++) {
                    float hval = (kk == 0) ? hv[mm].x : (kk == 1) ? hv[mm].y
                               : (kk == 2) ? hv[mm].z : hv[mm].w;
                    a0[mm] = fmaf(hval, w0, a0[mm]);
                    a1[mm] = fmaf(hval, w1, a1[mm]);
                    a2[mm] = fmaf(hval, w2, a2[mm]);
                }
            }
        }
        float hnew[4];
#pragma unroll
        for (int mm = 0; mm < 4; mm++) {
            float hold = h_s[(half * 4 + mm) * 128 + gpart];
            float r = 1.f / (1.f + expf(-(ir[mm] + a0[mm] + b0)));
            float z = 1.f / (1.f + expf(-(iz[mm] + a1[mm] + b1)));
            float n = tanhf(inp[mm] + r * (a2[mm] + b2));
            hnew[mm] = (1.f - z) * n + z * hold;
        }
        // half-block barrier: rows 0-3 touched only by warps 0-3 (and vice versa)
        asm volatile("bar.sync %0, 128;" :: "r"(half + 1) : "memory");
#pragma unroll
        for (int mm = 0; mm < 4; mm++) h_s[(half * 4 + mm) * 128 + gpart] = hnew[mm];
        asm volatile("bar.sync %0, 128;" :: "r"(half + 1) : "memory");

        if (writeHs) {
#pragma unroll
            for (int mm = 0; mm < 4; mm++)
                g_hs[(size_t)(r0 + half * 4 + mm) * (TT * HH) + (size_t)t * HH + gpart] = hnew[mm];
        } else {
#pragma unroll
            for (int mm = 0; mm < 4; mm++) msum[mm] += hnew[mm];
        }
    }
    if (!writeHs) {
#pragma unroll
        for (int mm = 0; mm < 4; mm++)
            g_hmean[(r0 + half * 4 + mm) * 128 + gpart] = msum[mm] * (1.f / 256.f);
    }
}

// ================= cosine similarity: partial gram over 16 k-slices =================
__global__ void __launch_bounds__(256) k_simpart(const float* __restrict__ x)
{
    const int s = blockIdx.x;   // k-slice
    const int b = blockIdx.y;   // batch
    __shared__ float Xs[64][65];
    const int tid = threadIdx.x;
    const int tr = (tid >> 4) * 4;
    const int tc = (tid & 15) * 4;
    float acc[4][4] = {};

    const float* xb = x + (size_t)b * NNODE * TD + (size_t)s * 2048;
    for (int c0 = 0; c0 < 2048; c0 += 64) {
#pragma unroll
        for (int l = 0; l < 16; l++) {
            int idx = tid + l * 256;
            int r = idx >> 6, c = idx & 63;
            Xs[r][c] = xb[(size_t)r * TD + c0 + c];
        }
        __syncthreads();
#pragma unroll 8
        for (int k = 0; k < 64; k++) {
            float a[4], bb[4];
#pragma unroll
            for (int i = 0; i < 4; i++) a[i] = Xs[tr + i][k];
#pragma unroll
            for (int j = 0; j < 4; j++) bb[j] = Xs[tc + j][k];
#pragma unroll
            for (int i = 0; i < 4; i++)
#pragma unroll
                for (int j = 0; j < 4; j++)
                    acc[i][j] = fmaf(a[i], bb[j], acc[i][j]);
        }
        __syncthreads();
    }
    float* gp = g_Gp + ((size_t)b * 16 + s) * 4096;
#pragma unroll
    for (int i = 0; i < 4; i++)
#pragma unroll
        for (int j = 0; j < 4; j++)
            gp[(tr + i) * 64 + tc + j] = acc[i][j];
}

__global__ void __launch_bounds__(256) k_simnorm()
{
    const int b = blockIdx.x;
    __shared__ float G[4096];
    const int tid = threadIdx.x;
    for (int i = tid; i < 4096; i += 256) {
        float v = 0.f;
#pragma unroll
        for (int s = 0; s < 16; s++) v += g_Gp[((size_t)b * 16 + s) * 4096 + i];
        G[i] = v;
    }
    __syncthreads();
    for (int i = tid; i < 4096; i += 256) {
        int r = i >> 6, c = i & 63;
        g_sim[(size_t)b * 4096 + i] = G[i] * rsqrtf(G[r * 64 + r] * G[c * 64 + c]);
    }
}

// ================= top-3 per row (strict > keeps earliest index, matches lax.top_k) ==
__global__ void k_topk()
{
    const int b = blockIdx.x, n = threadIdx.x;   // 64 threads
    const float* row = g_sim + (size_t)b * 4096 + n * 64;
    float v0 = -1e30f, v1 = -1e30f, v2 = -1e30f;
    int i0 = 0, i1 = 0, i2 = 0;
    for (int j = 0; j < 64; j++) {
        float v = row[j];
        if (v > v0)      { v2 = v1; i2 = i1; v1 = v0; i1 = i0; v0 = v; i0 = j; }
        else if (v > v1) { v2 = v1; i2 = i1; v1 = v;  i1 = j; }
        else if (v > v2) { v2 = v;  i2 = j; }
    }
    float* arow = g_A + (size_t)b * 4096 + n * 64;
    for (int j = 0; j < 64; j++) arow[j] = 0.f;
    arow[i0] = fmaxf(v0, 0.f);
    arow[i1] = fmaxf(v1, 0.f);
    arow[i2] = fmaxf(v2, 0.f);
}

__global__ void k_wbuild()
{
    const int b = blockIdx.x, tid = threadIdx.x;
    for (int i = tid; i < 4096; i += 256) {
        int r = i >> 6, c = i & 63;
        float v = (r == c) ? 1.f
                           : 0.5f * (g_A[(size_t)b * 4096 + i] + g_A[(size_t)b * 4096 + c * 64 + r]);
        g_w[(size_t)b * 4096 + i] = v;
    }
}

// ================= GINEConv layer (in-kernel nnW transpose to smem) =================
// layerSel=0: g_hmean -> g_h1 ;  layerSel=1: g_h1 -> g_h2
// dynamic smem: nnWs[128][129] + v[128]  -> 66560 B (opt-in)
__global__ void __launch_bounds__(128) k_gine(const float* __restrict__ eW,
                                              const float* __restrict__ eb,
                                              const float* __restrict__ nnW,
                                              const float* __restrict__ nnb,
                                              int layerSel)
{
    extern __shared__ float sg[];
    float* nnWs = sg;            // [k][c] transposed, pad 129
    float* v = sg + 128 * 129;
    const float* hin = layerSel ? (const float*)g_h1 : (const float*)g_hmean;
    float* hout      = layerSel ? (float*)g_h2 : (float*)g_h1;

    const int bj = blockIdx.x;
    const int b = bj >> 6, j = bj & 63;
    const int c = threadIdx.x;

    for (int i = c; i < 16384; i += 128) {
        int row = i >> 7, col = i & 127;       // nnW[row][col]
        nnWs[col * 129 + row] = nnW[i];        // nnWs[k=col][c=row]
    }

    const float We = eW[c], be = eb[c];
    float acc = 0.f;
    for (int i = 0; i < 64; i++) {
        float wv = g_w[(size_t)b * 4096 + i * 64 + j];
        if (wv > 0.f)
            acc += fmaxf(hin[(size_t)(b * 64 + i) * 128 + c] + wv * We + be, 0.f);
    }
    v[c] = hin[(size_t)(b * 64 + j) * 128 + c] + acc;
    __syncthreads();

    float o = nnb[c];
#pragma unroll 8
    for (int k = 0; k < 128; k++) o = fmaf(v[k], nnWs[k * 129 + c], o);
    hout[(size_t)(b * 64 + j) * 128 + c] = fmaxf(o, 0.f);
}

// ================= graph sum pool + classifier =================
__global__ void k_final(const float* __restrict__ clsW,
                        const float* __restrict__ clsb,
                        float* __restrict__ out)
{
    const int b = blockIdx.x, c = threadIdx.x;   // 128 threads
    float s = 0.f;
    for (int j = 0; j < 64; j++) s += g_h2[(size_t)(b * 64 + j) * 128 + c];
    s *= clsW[c];
    __shared__ float red[128];
    red[c] = s;
    __syncthreads();
    for (int off = 64; off > 0; off >>= 1) {
        if (c < off) red[c] += red[c + off];
        __syncthreads();
    }
    if (c == 0) out[b] = red[0] + clsb[0];
}

// ================= launch =================
extern "C" void kernel_launch(void* const* d_in, const int* in_sizes, int n_in,
                              void* d_out, int out_size)
{
    (void)out_size;
    // ---- input-order detection (signature vs alphabetical) via unique sizes ----
    int perm[15];
    for (int i = 0; i < 15; i++) perm[i] = i;
    if (n_in >= 15 && in_sizes[0] != 33554432 && in_sizes[14] == 33554432) {
        const int alpha[15] = {14, 6, 4, 10, 8, 7, 5, 11, 9, 2, 3, 12, 13, 0, 1};
        for (int i = 0; i < 15; i++) perm[i] = alpha[i];
    }
    const float* x     = (const float*)d_in[perm[0]];
    const float* Wih0  = (const float*)d_in[perm[1]];
    const float* Whh0  = (const float*)d_in[perm[2]];
    const float* bih0  = (const float*)d_in[perm[3]];
    const float* bhh0  = (const float*)d_in[perm[4]];
    const float* Wih1  = (const float*)d_in[perm[5]];
    const float* Whh1  = (const float*)d_in[perm[6]];
    const float* bih1  = (const float*)d_in[perm[7]];
    const float* bhh1  = (const float*)d_in[perm[8]];
    const float* edgeW = (const float*)d_in[perm[9]];
    const float* edgeb = (const float*)d_in[perm[10]];
    const float* nnW   = (const float*)d_in[perm[11]];
    const float* nnb   = (const float*)d_in[perm[12]];
    const float* clsW  = (const float*)d_in[perm[13]];
    const float* clsb  = (const float*)d_in[perm[14]];
    float* out = (float*)d_out;

    const int gruSmem  = (49152 + 8 * 128) * 4;          // 200704 B
    const int gineSmem = (128 * 129 + 128) * 4;          // 66560 B
    cudaFuncSetAttribute((const void*)k_gru_scan, cudaFuncAttributeMaxDynamicSharedMemorySize, gruSmem);
    cudaFuncSetAttribute((const void*)k_gine,     cudaFuncAttributeMaxDynamicSharedMemorySize, gineSmem);

    // ---- graph build (independent of GRU) ----
    dim3 gsp(16, BATCH);
    k_simpart<<<gsp, 256>>>(x);
    k_simnorm<<<BATCH, 256>>>();
    k_topk<<<BATCH, 64>>>();
    k_wbuild<<<BATCH, 256>>>();

    // ---- GRU layer 0 ----
    dim3 gg(2048, 3);
    k_gemm384<<<gg, 256>>>(x, Wih0, bih0, 0);            // gi = x @ Wih0^T + bih0
    k_gru_scan<<<128, 256, gruSmem>>>(Whh0, bhh0, 1);    // -> g_hs

    // ---- GRU layer 1 + mean pool ----
    k_gemm384<<<gg, 256>>>(x, Wih1, bih1, 1);            // gi = g_hs @ Wih1^T + bih1
    k_gru_scan<<<128, 256, gruSmem>>>(Whh1, bhh1, 0);    // -> g_hmean

    // ---- GINE layers ----
    k_gine<<<BN, 128, gineSmem>>>(edgeW,       edgeb,       nnW,         nnb,       0);
    k_gine<<<BN, 128, gineSmem>>>(edgeW + 128, edgeb + 128, nnW + 16384, nnb + 128, 1);

    // ---- pool + classifier ----
    k_final<<<BATCH, 128>>>(clsW, clsb, out);
}

// round 4
// speedup vs baseline: 1.0702x; 1.0702x over previous
#include <cuda_runtime.h>
#include <cuda_bf16.h>
#include <math.h>

// ---------------- problem constants ----------------
#define BATCH 16
#define NNODE 64
#define BN    1024      // BATCH*NNODE
#define TT    256
#define DD    128
#define HH    128
#define G3    384       // 3*H
#define TD    32768     // T*D

typedef unsigned long long ull;

// ---- f32x2 packed-math helpers (sm_103a dual-lane fp32 FMA) ----
#define FMA2(acc, a, b) asm("fma.rn.f32x2 %0, %1, %2, %0;" : "+l"(acc) : "l"(a), "l"(b))
#define PACKB(d, x)     asm("mov.b64 %0, {%1, %1};" : "=l"(d) : "f"(x))
#define PACK2(d, x, y)  asm("mov.b64 %0, {%1, %2};" : "=l"(d) : "f"(x), "f"(y))
#define UNPACK2(lo, hi, p) asm("mov.b64 {%0, %1}, %2;" : "=f"(lo), "=f"(hi) : "l"(p))
#define LDSV2U64(d0, d1, addr) \
    asm volatile("ld.shared.v2.u64 {%0, %1}, [%2];" : "=l"(d0), "=l"(d1) : "r"(addr))

__device__ __forceinline__ unsigned smem_u32(const void* p) {
    unsigned r;
    asm("{.reg .u64 t; cvta.to.shared.u64 t, %1; cvt.u32.u64 %0, t;}" : "=r"(r) : "l"(p));
    return r;
}

// ---------------- device scratch (NEVER referenced from host code!) ----------------
__device__ float g_gi[BN * TT * G3];        // gate inputs (reused both layers)
__device__ float g_hs[BN * TT * HH];        // layer-0 hidden sequence
__device__ float g_hmean[BN * HH];
__device__ float g_Gp[BATCH * 16 * NNODE * NNODE];
__device__ float g_sim[BATCH * NNODE * NNODE];
__device__ float g_A[BATCH * NNODE * NNODE];
__device__ float g_w[BATCH * NNODE * NNODE];
__device__ float g_h1[BN * HH];
__device__ float g_h2[BN * HH];

// ================= GEMM: g_gi[M,384] = A[M,128] @ W[384,128]^T + bias (f32x2) =========
__global__ void __launch_bounds__(256, 2) k_gemm384(const float* x_ext,
                                                    const float* __restrict__ W,
                                                    const float* __restrict__ bias,
                                                    int useHs)
{
    const float* A = useHs ? (const float*)g_hs : x_ext;
    __shared__ float As[16][132];
    __shared__ float Bs[16][132];
    const int bm = blockIdx.x * 128;
    const int bn = blockIdx.y * 128;
    const int tid = threadIdx.x;
    const int tr = (tid >> 4) * 8;
    const int tc = (tid & 15) * 8;

    // accumulators: row-pairs (tr+2ip, tr+2ip+1) x 8 cols, pre-init with bias
    ull accp[4][8];
#pragma unroll
    for (int j = 0; j < 8; j++) {
        float bj = bias[bn + tc + j];
        ull bb; PACKB(bb, bj);
#pragma unroll
        for (int ip = 0; ip < 4; ip++) accp[ip][j] = bb;
    }

    const unsigned aAddr = smem_u32(&As[0][0]) + tr * 4;

    for (int k0 = 0; k0 < 128; k0 += 16) {
#pragma unroll
        for (int l = 0; l < 2; l++) {
            int idx = tid + l * 256;           // 0..511
            int r = idx >> 2;
            int c4 = (idx & 3) * 4;
            float4 va = *(const float4*)&A[(size_t)(bm + r) * 128 + k0 + c4];
            As[c4 + 0][r] = va.x; As[c4 + 1][r] = va.y;
            As[c4 + 2][r] = va.z; As[c4 + 3][r] = va.w;
            float4 vb = *(const float4*)&W[(size_t)(bn + r) * 128 + k0 + c4];
            Bs[c4 + 0][r] = vb.x; Bs[c4 + 1][r] = vb.y;
            Bs[c4 + 2][r] = vb.z; Bs[c4 + 3][r] = vb.w;
        }
        __syncthreads();
#pragma unroll
        for (int k = 0; k < 16; k++) {
            ull a01, a23, a45, a67;
            LDSV2U64(a01, a23, aAddr + k * 528);
            LDSV2U64(a45, a67, aAddr + k * 528 + 16);
            float4 b0v = *(const float4*)&Bs[k][tc];
            float4 b1v = *(const float4*)&Bs[k][tc + 4];
            ull bp[8];
            PACKB(bp[0], b0v.x); PACKB(bp[1], b0v.y);
            PACKB(bp[2], b0v.z); PACKB(bp[3], b0v.w);
            PACKB(bp[4], b1v.x); PACKB(bp[5], b1v.y);
            PACKB(bp[6], b1v.z); PACKB(bp[7], b1v.w);
#pragma unroll
            for (int j = 0; j < 8; j++) {
                FMA2(accp[0][j], a01, bp[j]);
                FMA2(accp[1][j], a23, bp[j]);
                FMA2(accp[2][j], a45, bp[j]);
                FMA2(accp[3][j], a67, bp[j]);
            }
        }
        __syncthreads();
    }
    // unpack + store
    float cv[8][8];
#pragma unroll
    for (int ip = 0; ip < 4; ip++)
#pragma unroll
        for (int j = 0; j < 8; j++)
            UNPACK2(cv[2 * ip][j], cv[2 * ip + 1][j], accp[ip][j]);
#pragma unroll
    for (int i = 0; i < 8; i++) {
        float* cp = &g_gi[(size_t)(bm + tr + i) * G3 + bn + tc];
        *(float4*)&cp[0] = *(float4*)&cv[i][0];
        *(float4*)&cp[4] = *(float4*)&cv[i][4];
    }
}

// ================= GRU scan: persistent over T, 8 rows / CTA (f32x2) =================
// dynamic smem: whh_s[384][132] gate-major + h4[128][3] float4  -> 208896 B (opt-in)
__global__ void __launch_bounds__(256, 1) k_gru_scan(const float* __restrict__ Whh,
                                                     const float* __restrict__ bhh,
                                                     int writeHs)
{
    extern __shared__ float sm[];
    float* whh_s = sm;                         // [384][132]: whh_s[g*132+k] = Whh[g][k]
    float4* h4 = (float4*)(sm + 384 * 132);    // [128 k][3]: slot half in {0,1}, 2=pad

    const int tid = threadIdx.x;
    const int gpart = tid & 127;
    const int half = tid >> 7;         // 0: rows 0-3 (warps 0-3), 1: rows 4-7
    const int r0 = blockIdx.x * 8;

    for (int i = tid; i < 49152; i += 256) {
        int g = i >> 7, k = i & 127;
        whh_s[g * 132 + k] = Whh[i];
    }
    for (int i = tid; i < 128 * 3; i += 256) h4[i] = make_float4(0.f, 0.f, 0.f, 0.f);
    __syncthreads();

    const float b0 = bhh[gpart];
    const float b1 = bhh[gpart + 128];
    const float b2 = bhh[gpart + 256];
    float msum[4] = {0.f, 0.f, 0.f, 0.f};

    const unsigned h4a = smem_u32(h4) + half * 16;
    const unsigned w0a = smem_u32(whh_s) + gpart * 528;

    const float* gi_base = g_gi + (size_t)(r0 + half * 4) * (TT * G3);

    for (int t = 0; t < TT; t++) {
        float ir[4], iz[4], inp[4];
#pragma unroll
        for (int mm = 0; mm < 4; mm++) {
            const float* gp = gi_base + (size_t)mm * (TT * G3) + (size_t)t * G3;
            ir[mm]  = gp[gpart];
            iz[mm]  = gp[gpart + 128];
            inp[mm] = gp[gpart + 256];
        }
        ull A0 = 0, A1 = 0, B0 = 0, B1 = 0, C0 = 0, C1 = 0;  // (r,z,n) x (pair01, pair23)
#pragma unroll 4
        for (int k = 0; k < 128; k += 4) {
            float4 w0v = *(const float4*)(sm + gpart * 132 + k);               // gate r
            float4 w1v = *(const float4*)(sm + (gpart + 128) * 132 + k);       // gate z
            float4 w2v = *(const float4*)(sm + (gpart + 256) * 132 + k);       // gate n
#pragma unroll
            for (int kk = 0; kk < 4; kk++) {
                ull h01, h23;
                LDSV2U64(h01, h23, h4a + (k + kk) * 48);
                float w0 = (&w0v.x)[kk], w1 = (&w1v.x)[kk], w2 = (&w2v.x)[kk];
                ull w0p, w1p, w2p;
                PACKB(w0p, w0); PACKB(w1p, w1); PACKB(w2p, w2);
                FMA2(A0, h01, w0p); FMA2(A1, h23, w0p);
                FMA2(B0, h01, w1p); FMA2(B1, h23, w1p);
                FMA2(C0, h01, w2p); FMA2(C1, h23, w2p);
            }
        }
        float a0[4], a1[4], a2[4];
        UNPACK2(a0[0], a0[1], A0); UNPACK2(a0[2], a0[3], A1);
        UNPACK2(a1[0], a1[1], B0); UNPACK2(a1[2], a1[3], B1);
        UNPACK2(a2[0], a2[1], C0); UNPACK2(a2[2], a2[3], C1);

        float4 hold4 = h4[gpart * 3 + half];
        float hold[4] = {hold4.x, hold4.y, hold4.z, hold4.w};
        float hnew[4];
#pragma unroll
        for (int mm = 0; mm < 4; mm++) {
            float r = 1.f / (1.f + expf(-(ir[mm] + a0[mm] + b0)));
            float z = 1.f / (1.f + expf(-(iz[mm] + a1[mm] + b1)));
            float n = tanhf(inp[mm] + r * (a2[mm] + b2));
            hnew[mm] = (1.f - z) * n + z * hold[mm];
        }
        // half-block barrier: rows 0-3 touched only by warps 0-3 (and vice versa)
        asm volatile("bar.sync %0, 128;" :: "r"(half + 1) : "memory");
        h4[gpart * 3 + half] = make_float4(hnew[0], hnew[1], hnew[2], hnew[3]);
        asm volatile("bar.sync %0, 128;" :: "r"(half + 1) : "memory");

        if (writeHs) {
#pragma unroll
            for (int mm = 0; mm < 4; mm++)
                g_hs[(size_t)(r0 + half * 4 + mm) * (TT * HH) + (size_t)t * HH + gpart] = hnew[mm];
        } else {
#pragma unroll
            for (int mm = 0; mm < 4; mm++) msum[mm] += hnew[mm];
        }
    }
    if (!writeHs) {
#pragma unroll
        for (int mm = 0; mm < 4; mm++)
            g_hmean[(r0 + half * 4 + mm) * 128 + gpart] = msum[mm] * (1.f / 256.f);
    }
}

// ================= cosine similarity: partial gram over 16 k-slices (f32x2) ==========
__global__ void __launch_bounds__(256) k_simpart(const float* __restrict__ x)
{
    const int s = blockIdx.x;   // k-slice
    const int b = blockIdx.y;   // batch
    __shared__ float Xs[64 * 68];   // transposed: Xs[k][row], pad 68
    const int tid = threadIdx.x;
    const int tr = (tid >> 4) * 4;
    const int tc = (tid & 15) * 4;
    ull accp[2][4];
#pragma unroll
    for (int ip = 0; ip < 2; ip++)
#pragma unroll
        for (int j = 0; j < 4; j++) accp[ip][j] = 0ull;

    const unsigned aAddr = smem_u32(Xs) + tr * 4;

    const float* xb = x + (size_t)b * NNODE * TD + (size_t)s * 2048;
    for (int c0 = 0; c0 < 2048; c0 += 64) {
#pragma unroll
        for (int l = 0; l < 16; l++) {
            int idx = tid + l * 256;
            int r = idx >> 6, c = idx & 63;
            Xs[c * 68 + r] = xb[(size_t)r * TD + c0 + c];
        }
        __syncthreads();
#pragma unroll 4
        for (int k = 0; k < 64; k++) {
            ull a01, a23;
            LDSV2U64(a01, a23, aAddr + k * 272);
            float4 bv = *(const float4*)&Xs[k * 68 + tc];
            ull bp[4];
            PACKB(bp[0], bv.x); PACKB(bp[1], bv.y);
            PACKB(bp[2], bv.z); PACKB(bp[3], bv.w);
#pragma unroll
            for (int j = 0; j < 4; j++) {
                FMA2(accp[0][j], a01, bp[j]);
                FMA2(accp[1][j], a23, bp[j]);
            }
        }
        __syncthreads();
    }
    float acc[4][4];
#pragma unroll
    for (int ip = 0; ip < 2; ip++)
#pragma unroll
        for (int j = 0; j < 4; j++)
            UNPACK2(acc[2 * ip][j], acc[2 * ip + 1][j], accp[ip][j]);
    float* gp = g_Gp + ((size_t)b * 16 + s) * 4096;
#pragma unroll
    for (int i = 0; i < 4; i++)
#pragma unroll
        for (int j = 0; j < 4; j++)
            gp[(tr + i) * 64 + tc + j] = acc[i][j];
}

__global__ void __launch_bounds__(256) k_simnorm()
{
    const int b = blockIdx.x;
    __shared__ float G[4096];
    const int tid = threadIdx.x;
    for (int i = tid; i < 4096; i += 256) {
        float v = 0.f;
#pragma unroll
        for (int s = 0; s < 16; s++) v += g_Gp[((size_t)b * 16 + s) * 4096 + i];
        G[i] = v;
    }
    __syncthreads();
    for (int i = tid; i < 4096; i += 256) {
        int r = i >> 6, c = i & 63;
        g_sim[(size_t)b * 4096 + i] = G[i] * rsqrtf(G[r * 64 + r] * G[c * 64 + c]);
    }
}

// ================= top-3 per row (strict > keeps earliest index, matches lax.top_k) ==
__global__ void k_topk()
{
    const int b = blockIdx.x, n = threadIdx.x;   // 64 threads
    const float* row = g_sim + (size_t)b * 4096 + n * 64;
    float v0 = -1e30f, v1 = -1e30f, v2 = -1e30f;
    int i0 = 0, i1 = 0, i2 = 0;
    for (int j = 0; j < 64; j++) {
        float v = row[j];
        if (v > v0)      { v2 = v1; i2 = i1; v1 = v0; i1 = i0; v0 = v; i0 = j; }
        else if (v > v1) { v2 = v1; i2 = i1; v1 = v;  i1 = j; }
        else if (v > v2) { v2 = v;  i2 = j; }
    }
    float* arow = g_A + (size_t)b * 4096 + n * 64;
    for (int j = 0; j < 64; j++) arow[j] = 0.f;
    arow[i0] = fmaxf(v0, 0.f);
    arow[i1] = fmaxf(v1, 0.f);
    arow[i2] = fmaxf(v2, 0.f);
}

__global__ void k_wbuild()
{
    const int b = blockIdx.x, tid = threadIdx.x;
    for (int i = tid; i < 4096; i += 256) {
        int r = i >> 6, c = i & 63;
        float v = (r == c) ? 1.f
                           : 0.5f * (g_A[(size_t)b * 4096 + i] + g_A[(size_t)b * 4096 + c * 64 + r]);
        g_w[(size_t)b * 4096 + i] = v;
    }
}

// ================= GINEConv layer (nnW rows cached in smem, float4 math) =============
// layerSel=0: g_hmean -> g_h1 ;  layerSel=1: g_h1 -> g_h2
// dynamic smem: nnWs[128][132] + v[128]  -> 68096 B (opt-in)
__global__ void __launch_bounds__(128) k_gine(const float* __restrict__ eW,
                                              const float* __restrict__ eb,
                                              const float* __restrict__ nnW,
                                              const float* __restrict__ nnb,
                                              int layerSel)
{
    extern __shared__ float sg[];
    float* nnWs = sg;            // [c][k], pad 132
    float* v = sg + 128 * 132;
    const float* hin = layerSel ? (const float*)g_h1 : (const float*)g_hmean;
    float* hout      = layerSel ? (float*)g_h2 : (float*)g_h1;

    const int bj = blockIdx.x;
    const int b = bj >> 6, j = bj & 63;
    const int c = threadIdx.x;

    for (int i = c; i < 16384; i += 128) {
        int row = i >> 7, col = i & 127;       // nnW[row][col]
        nnWs[row * 132 + col] = nnW[i];        // o_c = sum_k v[k]*nnW[c][k]
    }

    const float We = eW[c], be = eb[c];
    float acc = 0.f;
    for (int i = 0; i < 64; i++) {
        float wv = g_w[(size_t)b * 4096 + i * 64 + j];
        if (wv > 0.f)
            acc += fmaxf(hin[(size_t)(b * 64 + i) * 128 + c] + wv * We + be, 0.f);
    }
    v[c] = hin[(size_t)(b * 64 + j) * 128 + c] + acc;
    __syncthreads();

    float o = nnb[c];
#pragma unroll
    for (int k = 0; k < 128; k += 4) {
        float4 wv4 = *(const float4*)&nnWs[c * 132 + k];
        float4 vv4 = *(const float4*)&v[k];
        o = fmaf(vv4.x, wv4.x, o);
        o = fmaf(vv4.y, wv4.y, o);
        o = fmaf(vv4.z, wv4.z, o);
        o = fmaf(vv4.w, wv4.w, o);
    }
    hout[(size_t)(b * 64 + j) * 128 + c] = fmaxf(o, 0.f);
}

// ================= graph sum pool + classifier =================
__global__ void k_final(const float* __restrict__ clsW,
                        const float* __restrict__ clsb,
                        float* __restrict__ out)
{
    const int b = blockIdx.x, c = threadIdx.x;   // 128 threads
    float s = 0.f;
    for (int j = 0; j < 64; j++) s += g_h2[(size_t)(b * 64 + j) * 128 + c];
    s *= clsW[c];
    __shared__ float red[128];
    red[c] = s;
    __syncthreads();
    for (int off = 64; off > 0; off >>= 1) {
        if (c < off) red[c] += red[c + off];
        __syncthreads();
    }
    if (c == 0) out[b] = red[0] + clsb[0];
}

// ================= launch =================
extern "C" void kernel_launch(void* const* d_in, const int* in_sizes, int n_in,
                              void* d_out, int out_size)
{
    (void)out_size;
    // ---- input-order detection (signature vs alphabetical) via unique sizes ----
    int perm[15];
    for (int i = 0; i < 15; i++) perm[i] = i;
    if (n_in >= 15 && in_sizes[0] != 33554432 && in_sizes[14] == 33554432) {
        const int alpha[15] = {14, 6, 4, 10, 8, 7, 5, 11, 9, 2, 3, 12, 13, 0, 1};
        for (int i = 0; i < 15; i++) perm[i] = alpha[i];
    }
    const float* x     = (const float*)d_in[perm[0]];
    const float* Wih0  = (const float*)d_in[perm[1]];
    const float* Whh0  = (const float*)d_in[perm[2]];
    const float* bih0  = (const float*)d_in[perm[3]];
    const float* bhh0  = (const float*)d_in[perm[4]];
    const float* Wih1  = (const float*)d_in[perm[5]];
    const float* Whh1  = (const float*)d_in[perm[6]];
    const float* bih1  = (const float*)d_in[perm[7]];
    const float* bhh1  = (const float*)d_in[perm[8]];
    const float* edgeW = (const float*)d_in[perm[9]];
    const float* edgeb = (const float*)d_in[perm[10]];
    const float* nnW   = (const float*)d_in[perm[11]];
    const float* nnb   = (const float*)d_in[perm[12]];
    const float* clsW  = (const float*)d_in[perm[13]];
    const float* clsb  = (const float*)d_in[perm[14]];
    float* out = (float*)d_out;

    const int gruSmem  = (384 * 132 + 128 * 3 * 4) * 4;   // 208896 B
    const int gineSmem = (128 * 132 + 128) * 4;            // 68096 B
    cudaFuncSetAttribute((const void*)k_gru_scan, cudaFuncAttributeMaxDynamicSharedMemorySize, gruSmem);
    cudaFuncSetAttribute((const void*)k_gine,     cudaFuncAttributeMaxDynamicSharedMemorySize, gineSmem);

    // ---- graph build (independent of GRU) ----
    dim3 gsp(16, BATCH);
    k_simpart<<<gsp, 256>>>(x);
    k_simnorm<<<BATCH, 256>>>();
    k_topk<<<BATCH, 64>>>();
    k_wbuild<<<BATCH, 256>>>();

    // ---- GRU layer 0 ----
    dim3 gg(2048, 3);
    k_gemm384<<<gg, 256>>>(x, Wih0, bih0, 0);            // gi = x @ Wih0^T + bih0
    k_gru_scan<<<128, 256, gruSmem>>>(Whh0, bhh0, 1);    // -> g_hs

    // ---- GRU layer 1 + mean pool ----
    k_gemm384<<<gg, 256>>>(x, Wih1, bih1, 1);            // gi = g_hs @ Wih1^T + bih1
    k_gru_scan<<<128, 256, gruSmem>>>(Whh1, bhh1, 0);    // -> g_hmean

    // ---- GINE layers ----
    k_gine<<<BN, 128, gineSmem>>>(edgeW,       edgeb,       nnW,         nnb,       0);
    k_gine<<<BN, 128, gineSmem>>>(edgeW + 128, edgeb + 128, nnW + 16384, nnb + 128, 1);

    // ---- pool + classifier ----
    k_final<<<BATCH, 128>>>(clsW, clsb, out);
}

// round 6
// speedup vs baseline: 1.3104x; 1.2244x over previous
#include <cuda_runtime.h>
#include <cuda_bf16.h>
#include <math.h>
#include <stdint.h>

// ---------------- problem constants ----------------
#define BATCH 16
#define NNODE 64
#define BN    1024      // BATCH*NNODE
#define TT    256
#define DD    128
#define HH    128
#define G3    384       // 3*H
#define TD    32768     // T*D
#define MROWS (BN * TT) // 262144 GEMM rows

typedef unsigned long long ull;

// ---- f32x2 packed-math helpers ----
#define FMA2(acc, a, b) asm("fma.rn.f32x2 %0, %1, %2, %0;" : "+l"(acc) : "l"(a), "l"(b))
#define PACKB(d, x)     asm("mov.b64 %0, {%1, %1};" : "=l"(d) : "f"(x))
#define UNPACK2(lo, hi, p) asm("mov.b64 {%0, %1}, %2;" : "=f"(lo), "=f"(hi) : "l"(p))
#define LDSV2U64(d0, d1, addr) \
    asm volatile("ld.shared.v2.u64 {%0, %1}, [%2];" : "=l"(d0), "=l"(d1) : "r"(addr))

__device__ __forceinline__ unsigned smem_u32(const void* p) {
    unsigned r;
    asm("{.reg .u64 t; cvta.to.shared.u64 t, %1; cvt.u32.u64 %0, t;}" : "=r"(r) : "l"(p));
    return r;
}

// ---- warp-level tensor core ops (baseline sm_80+ PTX; no 'a' feature needed) ----
#define LDSM_X4(r0, r1, r2, r3, addr) \
    asm volatile("ldmatrix.sync.aligned.m8n8.x4.shared.b16 {%0,%1,%2,%3},[%4];" \
        : "=r"(r0), "=r"(r1), "=r"(r2), "=r"(r3) : "r"(addr))
#define LDSM_X2(r0, r1, addr) \
    asm volatile("ldmatrix.sync.aligned.m8n8.x2.shared.b16 {%0,%1},[%2];" \
        : "=r"(r0), "=r"(r1) : "r"(addr))
#define MMA16816(d, a0, a1, a2, a3, b0, b1) \
    asm volatile("mma.sync.aligned.m16n8k16.row.col.f32.bf16.bf16.f32 " \
        "{%0,%1,%2,%3},{%4,%5,%6,%7},{%8,%9},{%0,%1,%2,%3};" \
        : "+f"((d)[0]), "+f"((d)[1]), "+f"((d)[2]), "+f"((d)[3]) \
        : "r"(a0), "r"(a1), "r"(a2), "r"(a3), "r"(b0), "r"(b1))

// ---------------- device scratch (NEVER referenced from host code!) ----------------
__device__ float g_gi[MROWS * G3];           // gate inputs (reused both layers)
__device__ float g_hs[MROWS * HH];           // layer-0 hidden sequence
__device__ float g_hmean[BN * HH];
__device__ float g_Gp[BATCH * 16 * NNODE * NNODE];
__device__ float g_sim[BATCH * NNODE * NNODE];
__device__ float g_A[BATCH * NNODE * NNODE];
__device__ float g_w[BATCH * NNODE * NNODE];
__device__ float g_h1[BN * HH];
__device__ float g_h2[BN * HH];
__device__ __nv_bfloat16 g_ahi[MROWS * DD];  // A hi split (x or g_hs)
__device__ __nv_bfloat16 g_alo[MROWS * DD];  // A lo split
__device__ __nv_bfloat16 g_whi[G3 * DD];     // Wih hi split
__device__ __nv_bfloat16 g_wlo[G3 * DD];     // Wih lo split

// ================= fp32 -> bf16 hi/lo split converters =================
// mode 0: src = x_ext (MROWS*DD elems) -> g_ahi/g_alo
// mode 1: src = g_hs                   -> g_ahi/g_alo
// mode 2: src = W_ext (G3*DD elems)    -> g_whi/g_wlo
__global__ void __launch_bounds__(256) k_cvt(const float* src_ext, int mode)
{
    const float* src = (mode == 1) ? (const float*)g_hs : src_ext;
    __nv_bfloat16* dhi = (mode == 2) ? g_whi : g_ahi;
    __nv_bfloat16* dlo = (mode == 2) ? g_wlo : g_alo;
    const int n4 = (mode == 2) ? (G3 * DD / 4) : (MROWS * DD / 4);

    for (int i = blockIdx.x * 256 + threadIdx.x; i < n4; i += gridDim.x * 256) {
        float4 v = *(const float4*)&src[i * 4];
        __nv_bfloat162 h0 = __float22bfloat162_rn(make_float2(v.x, v.y));
        __nv_bfloat162 h1 = __float22bfloat162_rn(make_float2(v.z, v.w));
        float2 r0 = make_float2(v.x - __bfloat162float(h0.x), v.y - __bfloat162float(h0.y));
        float2 r1 = make_float2(v.z - __bfloat162float(h1.x), v.w - __bfloat162float(h1.y));
        __nv_bfloat162 l0 = __float22bfloat162_rn(r0);
        __nv_bfloat162 l1 = __float22bfloat162_rn(r1);
        *(__nv_bfloat162*)&dhi[i * 4]     = h0;
        *(__nv_bfloat162*)&dhi[i * 4 + 2] = h1;
        *(__nv_bfloat162*)&dlo[i * 4]     = l0;
        *(__nv_bfloat162*)&dlo[i * 4 + 2] = l1;
    }
}

// ================= tensor-core GEMM: g_gi[M,384] = A @ W^T + bias ====================
// bf16 hi/lo 3-split via mma.sync m16n8k16. CTA: 128 rows x 384 cols (loop 6 n-tiles of 64).
// smem: A[2 split][128][136] bf16 (69632 B) + B[2 split][64][136] bf16 (34816 B) = 104448 B
#define GM_ASTRIDE 136
#define GM_ASPLIT  (128 * GM_ASTRIDE * 2)   // bytes per A split
#define GM_BSPLIT  (64 * GM_ASTRIDE * 2)    // bytes per B split
#define GM_BOFF    (2 * GM_ASPLIT)
#define GM_SMEM    (GM_BOFF + 2 * GM_BSPLIT)

__global__ void __launch_bounds__(256, 1) k_gemm_mma(const float* __restrict__ bias)
{
    extern __shared__ char smg[];
    const uint32_t sbase = smem_u32(smg);
    const int tid  = threadIdx.x;
    const int w    = tid >> 5;
    const int lane = tid & 31;
    const int bm   = blockIdx.x * 128;

    // ---- load A tile (both splits) into padded smem ----
    for (int i = tid; i < 4096; i += 256) {          // 2048 uint4 per split
        int s   = i >> 11;
        int rem = i & 2047;
        int row = rem >> 4;                          // 128 rows
        int c8  = (rem & 15) << 3;                   // col in bf16, step 8
        const uint4 v = *(const uint4*)((s ? g_alo : g_ahi) + (size_t)(bm + row) * DD + c8);
        *(uint4*)(smg + s * GM_ASPLIT + (row * GM_ASTRIDE + c8) * 2) = v;
    }

    const int mbase = (w & 3) * 32;                  // warp m offset (2 m16 tiles)
    const int nwb   = (w >> 2) * 32;                 // warp n offset within 64-col tile
    const int g = lane >> 2, t = lane & 3;

    // ldmatrix lane addresses (byte offsets within a split)
    const int aRow = lane & 15, aCol = (lane >> 4) << 3;
    const uint32_t aAddrBase = sbase + ((mbase + aRow) * GM_ASTRIDE + aCol) * 2;
    const int bRow = lane & 7, bCol = ((lane >> 3) & 1) << 3;
    const uint32_t bAddrBase = sbase + GM_BOFF + (bRow * GM_ASTRIDE + bCol) * 2;

    const int spA[3] = {0, 0, 1};                    // split pairs: (Ah,Bh),(Ah,Bl),(Al,Bh)
    const int spB[3] = {0, 1, 0};

    for (int nt = 0; nt < 6; nt++) {
        // ---- stage B n-tile (64 rows of W, both splits) ----
        for (int i = tid; i < 2048; i += 256) {      // 1024 uint4 per split
            int s   = i >> 10;
            int rem = i & 1023;
            int row = rem >> 4;                      // 64 rows
            int c8  = (rem & 15) << 3;
            const uint4 v = *(const uint4*)((s ? g_wlo : g_whi) + (size_t)(nt * 64 + row) * DD + c8);
            *(uint4*)(smg + GM_BOFF + s * GM_BSPLIT + (row * GM_ASTRIDE + c8) * 2) = v;
        }
        __syncthreads();

        float acc[2][4][4];
#pragma unroll
        for (int mt = 0; mt < 2; mt++)
#pragma unroll
            for (int nb = 0; nb < 4; nb++)
#pragma unroll
                for (int r = 0; r < 4; r++) acc[mt][nb][r] = 0.f;

#pragma unroll
        for (int p = 0; p < 3; p++) {
            const uint32_t aA = aAddrBase + spA[p] * GM_ASPLIT;
            const uint32_t bA = bAddrBase + spB[p] * GM_BSPLIT;
#pragma unroll
            for (int k = 0; k < 8; k++) {
                uint32_t a0[4], a1[4];
                LDSM_X4(a0[0], a0[1], a0[2], a0[3], aA + k * 32);
                LDSM_X4(a1[0], a1[1], a1[2], a1[3], aA + 16 * GM_ASTRIDE * 2 + k * 32);
#pragma unroll
                for (int nb = 0; nb < 4; nb++) {
                    uint32_t b0, b1;
                    LDSM_X2(b0, b1, bA + (nwb + nb * 8) * GM_ASTRIDE * 2 + k * 32);
                    MMA16816(acc[0][nb], a0[0], a0[1], a0[2], a0[3], b0, b1);
                    MMA16816(acc[1][nb], a1[0], a1[1], a1[2], a1[3], b0, b1);
                }
            }
        }

        // ---- epilogue: bias + store ----
        const int colb = nt * 64 + nwb;
#pragma unroll
        for (int mt = 0; mt < 2; mt++) {
            const int row0 = bm + mbase + mt * 16 + g;
#pragma unroll
            for (int nb = 0; nb < 4; nb++) {
                const int col = colb + nb * 8 + 2 * t;
                const float bx = __ldg(&bias[col]);
                const float by = __ldg(&bias[col + 1]);
                float2 v0 = make_float2(acc[mt][nb][0] + bx, acc[mt][nb][1] + by);
                float2 v1 = make_float2(acc[mt][nb][2] + bx, acc[mt][nb][3] + by);
                *(float2*)&g_gi[(size_t)row0 * G3 + col]       = v0;
                *(float2*)&g_gi[(size_t)(row0 + 8) * G3 + col] = v1;
            }
        }
        __syncthreads();
    }
}

// ================= GRU scan: persistent over T, 8 rows / CTA (f32x2) =================
__global__ void __launch_bounds__(256, 1) k_gru_scan(const float* __restrict__ Whh,
                                                     const float* __restrict__ bhh,
                                                     int writeHs)
{
    extern __shared__ float sm[];
    float* whh_s = sm;                         // [384][132]: whh_s[g*132+k] = Whh[g][k]
    float4* h4 = (float4*)(sm + 384 * 132);    // [128 k][3]: slot half in {0,1}, 2=pad

    const int tid = threadIdx.x;
    const int gpart = tid & 127;
    const int half = tid >> 7;
    const int r0 = blockIdx.x * 8;

    for (int i = tid; i < 49152; i += 256) {
        int g = i >> 7, k = i & 127;
        whh_s[g * 132 + k] = Whh[i];
    }
    for (int i = tid; i < 128 * 3; i += 256) h4[i] = make_float4(0.f, 0.f, 0.f, 0.f);
    __syncthreads();

    const float b0 = bhh[gpart];
    const float b1 = bhh[gpart + 128];
    const float b2 = bhh[gpart + 256];
    float msum[4] = {0.f, 0.f, 0.f, 0.f};

    const unsigned h4a = smem_u32(h4) + half * 16;

    const float* gi_base = g_gi + (size_t)(r0 + half * 4) * (TT * G3);

    for (int t = 0; t < TT; t++) {
        float ir[4], iz[4], inp[4];
#pragma unroll
        for (int mm = 0; mm < 4; mm++) {
            const float* gp = gi_base + (size_t)mm * (TT * G3) + (size_t)t * G3;
            ir[mm]  = gp[gpart];
            iz[mm]  = gp[gpart + 128];
            inp[mm] = gp[gpart + 256];
        }
        ull A0 = 0, A1 = 0, B0 = 0, B1 = 0, C0 = 0, C1 = 0;
#pragma unroll 4
        for (int k = 0; k < 128; k += 4) {
            float4 w0v = *(const float4*)(sm + gpart * 132 + k);
            float4 w1v = *(const float4*)(sm + (gpart + 128) * 132 + k);
            float4 w2v = *(const float4*)(sm + (gpart + 256) * 132 + k);
#pragma unroll
            for (int kk = 0; kk < 4; kk++) {
                ull h01, h23;
                LDSV2U64(h01, h23, h4a + (k + kk) * 48);
                float w0 = (&w0v.x)[kk], w1 = (&w1v.x)[kk], w2 = (&w2v.x)[kk];
                ull w0p, w1p, w2p;
                PACKB(w0p, w0); PACKB(w1p, w1); PACKB(w2p, w2);
                FMA2(A0, h01, w0p); FMA2(A1, h23, w0p);
                FMA2(B0, h01, w1p); FMA2(B1, h23, w1p);
                FMA2(C0, h01, w2p); FMA2(C1, h23, w2p);
            }
        }
        float a0[4], a1[4], a2[4];
        UNPACK2(a0[0], a0[1], A0); UNPACK2(a0[2], a0[3], A1);
        UNPACK2(a1[0], a1[1], B0); UNPACK2(a1[2], a1[3], B1);
        UNPACK2(a2[0], a2[1], C0); UNPACK2(a2[2], a2[3], C1);

        float4 hold4 = h4[gpart * 3 + half];
        float hold[4] = {hold4.x, hold4.y, hold4.z, hold4.w};
        float hnew[4];
#pragma unroll
        for (int mm = 0; mm < 4; mm++) {
            float r = __fdividef(1.f, 1.f + __expf(-(ir[mm] + a0[mm] + b0)));
            float z = __fdividef(1.f, 1.f + __expf(-(iz[mm] + a1[mm] + b1)));
            float u = inp[mm] + r * (a2[mm] + b2);
            float n = 1.f - __fdividef(2.f, __expf(u + u) + 1.f);
            hnew[mm] = (1.f - z) * n + z * hold[mm];
        }
        asm volatile("bar.sync %0, 128;" :: "r"(half + 1) : "memory");
        h4[gpart * 3 + half] = make_float4(hnew[0], hnew[1], hnew[2], hnew[3]);
        asm volatile("bar.sync %0, 128;" :: "r"(half + 1) : "memory");

        if (writeHs) {
#pragma unroll
            for (int mm = 0; mm < 4; mm++)
                g_hs[(size_t)(r0 + half * 4 + mm) * (TT * HH) + (size_t)t * HH + gpart] = hnew[mm];
        } else {
#pragma unroll
            for (int mm = 0; mm < 4; mm++) msum[mm] += hnew[mm];
        }
    }
    if (!writeHs) {
#pragma unroll
        for (int mm = 0; mm < 4; mm++)
            g_hmean[(r0 + half * 4 + mm) * 128 + gpart] = msum[mm] * (1.f / 256.f);
    }
}

// ================= cosine similarity: partial gram over 16 k-slices (f32x2) ==========
__global__ void __launch_bounds__(256) k_simpart(const float* __restrict__ x)
{
    const int s = blockIdx.x;
    const int b = blockIdx.y;
    __shared__ float Xs[64 * 68];
    const int tid = threadIdx.x;
    const int tr = (tid >> 4) * 4;
    const int tc = (tid & 15) * 4;
    ull accp[2][4];
#pragma unroll
    for (int ip = 0; ip < 2; ip++)
#pragma unroll
        for (int j = 0; j < 4; j++) accp[ip][j] = 0ull;

    const unsigned aAddr = smem_u32(Xs) + tr * 4;

    const float* xb = x + (size_t)b * NNODE * TD + (size_t)s * 2048;
    for (int c0 = 0; c0 < 2048; c0 += 64) {
#pragma unroll
        for (int l = 0; l < 16; l++) {
            int idx = tid + l * 256;
            int r = idx >> 6, c = idx & 63;
            Xs[c * 68 + r] = xb[(size_t)r * TD + c0 + c];
        }
        __syncthreads();
#pragma unroll 4
        for (int k = 0; k < 64; k++) {
            ull a01, a23;
            LDSV2U64(a01, a23, aAddr + k * 272);
            float4 bv = *(const float4*)&Xs[k * 68 + tc];
            ull bp[4];
            PACKB(bp[0], bv.x); PACKB(bp[1], bv.y);
            PACKB(bp[2], bv.z); PACKB(bp[3], bv.w);
#pragma unroll
            for (int j = 0; j < 4; j++) {
                FMA2(accp[0][j], a01, bp[j]);
                FMA2(accp[1][j], a23, bp[j]);
            }
        }
        __syncthreads();
    }
    float acc[4][4];
#pragma unroll
    for (int ip = 0; ip < 2; ip++)
#pragma unroll
        for (int j = 0; j < 4; j++)
            UNPACK2(acc[2 * ip][j], acc[2 * ip + 1][j], accp[ip][j]);
    float* gp = g_Gp + ((size_t)b * 16 + s) * 4096;
#pragma unroll
    for (int i = 0; i < 4; i++)
#pragma unroll
        for (int j = 0; j < 4; j++)
            gp[(tr + i) * 64 + tc + j] = acc[i][j];
}

__global__ void __launch_bounds__(256) k_simnorm()
{
    const int b = blockIdx.x;
    __shared__ float G[4096];
    const int tid = threadIdx.x;
    for (int i = tid; i < 4096; i += 256) {
        float v = 0.f;
#pragma unroll
        for (int s = 0; s < 16; s++) v += g_Gp[((size_t)b * 16 + s) * 4096 + i];
        G[i] = v;
    }
    __syncthreads();
    for (int i = tid; i < 4096; i += 256) {
        int r = i >> 6, c = i & 63;
        g_sim[(size_t)b * 4096 + i] = G[i] * rsqrtf(G[r * 64 + r] * G[c * 64 + c]);
    }
}

// ================= top-3 per row =================
__global__ void k_topk()
{
    const int b = blockIdx.x, n = threadIdx.x;
    const float* row = g_sim + (size_t)b * 4096 + n * 64;
    float v0 = -1e30f, v1 = -1e30f, v2 = -1e30f;
    int i0 = 0, i1 = 0, i2 = 0;
    for (int j = 0; j < 64; j++) {
        float v = row[j];
        if (v > v0)      { v2 = v1; i2 = i1; v1 = v0; i1 = i0; v0 = v; i0 = j; }
        else if (v > v1) { v2 = v1; i2 = i1; v1 = v;  i1 = j; }
        else if (v > v2) { v2 = v;  i2 = j; }
    }
    float* arow = g_A + (size_t)b * 4096 + n * 64;
    for (int j = 0; j < 64; j++) arow[j] = 0.f;
    arow[i0] = fmaxf(v0, 0.f);
    arow[i1] = fmaxf(v1, 0.f);
    arow[i2] = fmaxf(v2, 0.f);
}

__global__ void k_wbuild()
{
    const int b = blockIdx.x, tid = threadIdx.x;
    for (int i = tid; i < 4096; i += 256) {
        int r = i >> 6, c = i & 63;
        float v = (r == c) ? 1.f
                           : 0.5f * (g_A[(size_t)b * 4096 + i] + g_A[(size_t)b * 4096 + c * 64 + r]);
        g_w[(size_t)b * 4096 + i] = v;
    }
}

// ================= GINEConv layer =================
__global__ void __launch_bounds__(128) k_gine(const float* __restrict__ eW,
                                              const float* __restrict__ eb,
                                              const float* __restrict__ nnW,
                                              const float* __restrict__ nnb,
                                              int layerSel)
{
    extern __shared__ float sg[];
    float* nnWs = sg;            // [c][k], pad 132
    float* v = sg + 128 * 132;
    const float* hin = layerSel ? (const float*)g_h1 : (const float*)g_hmean;
    float* hout      = layerSel ? (float*)g_h2 : (float*)g_h1;

    const int bj = blockIdx.x;
    const int b = bj >> 6, j = bj & 63;
    const int c = threadIdx.x;

    for (int i = c; i < 16384; i += 128) {
        int row = i >> 7, col = i & 127;
        nnWs[row * 132 + col] = nnW[i];
    }

    const float We = eW[c], be = eb[c];
    float acc = 0.f;
    for (int i = 0; i < 64; i++) {
        float wv = g_w[(size_t)b * 4096 + i * 64 + j];
        if (wv > 0.f)
            acc += fmaxf(hin[(size_t)(b * 64 + i) * 128 + c] + wv * We + be, 0.f);
    }
    v[c] = hin[(size_t)(b * 64 + j) * 128 + c] + acc;
    __syncthreads();

    float o = nnb[c];
#pragma unroll
    for (int k = 0; k < 128; k += 4) {
        float4 wv4 = *(const float4*)&nnWs[c * 132 + k];
        float4 vv4 = *(const float4*)&v[k];
        o = fmaf(vv4.x, wv4.x, o);
        o = fmaf(vv4.y, wv4.y, o);
        o = fmaf(vv4.z, wv4.z, o);
        o = fmaf(vv4.w, wv4.w, o);
    }
    hout[(size_t)(b * 64 + j) * 128 + c] = fmaxf(o, 0.f);
}

// ================= graph sum pool + classifier =================
__global__ void k_final(const float* __restrict__ clsW,
                        const float* __restrict__ clsb,
                        float* __restrict__ out)
{
    const int b = blockIdx.x, c = threadIdx.x;
    float s = 0.f;
    for (int j = 0; j < 64; j++) s += g_h2[(size_t)(b * 64 + j) * 128 + c];
    s *= clsW[c];
    __shared__ float red[128];
    red[c] = s;
    __syncthreads();
    for (int off = 64; off > 0; off >>= 1) {
        if (c < off) red[c] += red[c + off];
        __syncthreads();
    }
    if (c == 0) out[b] = red[0] + clsb[0];
}

// ================= launch =================
extern "C" void kernel_launch(void* const* d_in, const int* in_sizes, int n_in,
                              void* d_out, int out_size)
{
    (void)out_size;
    int perm[15];
    for (int i = 0; i < 15; i++) perm[i] = i;
    if (n_in >= 15 && in_sizes[0] != 33554432 && in_sizes[14] == 33554432) {
        const int alpha[15] = {14, 6, 4, 10, 8, 7, 5, 11, 9, 2, 3, 12, 13, 0, 1};
        for (int i = 0; i < 15; i++) perm[i] = alpha[i];
    }
    const float* x     = (const float*)d_in[perm[0]];
    const float* Wih0  = (const float*)d_in[perm[1]];
    const float* Whh0  = (const float*)d_in[perm[2]];
    const float* bih0  = (const float*)d_in[perm[3]];
    const float* bhh0  = (const float*)d_in[perm[4]];
    const float* Wih1  = (const float*)d_in[perm[5]];
    const float* Whh1  = (const float*)d_in[perm[6]];
    const float* bih1  = (const float*)d_in[perm[7]];
    const float* bhh1  = (const float*)d_in[perm[8]];
    const float* edgeW = (const float*)d_in[perm[9]];
    const float* edgeb = (const float*)d_in[perm[10]];
    const float* nnW   = (const float*)d_in[perm[11]];
    const float* nnb   = (const float*)d_in[perm[12]];
    const float* clsW  = (const float*)d_in[perm[13]];
    const float* clsb  = (const float*)d_in[perm[14]];
    float* out = (float*)d_out;

    const int gruSmem  = (384 * 132 + 128 * 3 * 4) * 4;    // 208896 B
    const int gineSmem = (128 * 132 + 128) * 4;            // 68096 B
    cudaFuncSetAttribute((const void*)k_gru_scan, cudaFuncAttributeMaxDynamicSharedMemorySize, gruSmem);
    cudaFuncSetAttribute((const void*)k_gine,     cudaFuncAttributeMaxDynamicSharedMemorySize, gineSmem);
    cudaFuncSetAttribute((const void*)k_gemm_mma, cudaFuncAttributeMaxDynamicSharedMemorySize, GM_SMEM);

    // ---- graph build (independent of GRU) ----
    dim3 gsp(16, BATCH);
    k_simpart<<<gsp, 256>>>(x);
    k_simnorm<<<BATCH, 256>>>();
    k_topk<<<BATCH, 64>>>();
    k_wbuild<<<BATCH, 256>>>();

    // ---- GRU layer 0 ----
    k_cvt<<<4096, 256>>>(x, 0);                            // x -> bf16 hi/lo
    k_cvt<<<64, 256>>>(Wih0, 2);                           // Wih0 -> bf16 hi/lo
    k_gemm_mma<<<2048, 256, GM_SMEM>>>(bih0);              // gi = x @ Wih0^T + bih0
    k_gru_scan<<<128, 256, gruSmem>>>(Whh0, bhh0, 1);      // -> g_hs

    // ---- GRU layer 1 + mean pool ----
    k_cvt<<<4096, 256>>>(x, 1);                            // g_hs -> bf16 hi/lo
    k_cvt<<<64, 256>>>(Wih1, 2);                           // Wih1 -> bf16 hi/lo
    k_gemm_mma<<<2048, 256, GM_SMEM>>>(bih1);              // gi = g_hs @ Wih1^T + bih1
    k_gru_scan<<<128, 256, gruSmem>>>(Whh1, bhh1, 0);      // -> g_hmean

    // ---- GINE layers ----
    k_gine<<<BN, 128, gineSmem>>>(edgeW,       edgeb,       nnW,         nnb,       0);
    k_gine<<<BN, 128, gineSmem>>>(edgeW + 128, edgeb + 128, nnW + 16384, nnb + 128, 1);

    // ---- pool + classifier ----
    k_final<<<BATCH, 128>>>(clsW, clsb, out);
}